// round 12
// baseline (speedup 1.0000x reference)
#include <cuda_runtime.h>
#include <math.h>
#include <stdint.h>

#define VOCAB   30522
#define NROWS   4096
#define DIM     768
#define P_LINE  224
#define N_LINE  224
#define P_QUAT  64
#define N_QUAT  64
#define B_SON   16
#define TEMP_INV (1.0f/0.07f)

#define W_MLM    0.5f
#define W_LINE   0.2f
#define W_QUAT   0.2f
#define W_SONNET 0.1f

// global anchor index space: line [0,224), quat [224,288), sonnet [288,304)
#define NANCH    304
#define MAXCHUNK 8
// small-path blocks: 196 line (28 groups x 7 chunks) + 16 quat (8x2) + 2 sonnet
#define SMALL_BLOCKS 214
// persistent MLM workers: 148 SMs x 5 CTAs (reg-limited occupancy)
#define MLM_WORKERS  740
#define GRID_MAIN    (SMALL_BLOCKS + MLM_WORKERS)
#define BATCH        2                   // rows per steal

// ---- scratch (__device__ globals; no allocations allowed) ----
__device__ float2       g_nv[NROWS];        // {nll, valid} — one write per row
__device__ float        g_pos[NANCH];
__device__ float        g_part[NANCH * MAXCHUNK];
__device__ int          g_next  = 0;        // row work-stealing counter
__device__ unsigned int g_count = 0;        // arrival counter (last-block-done)

__device__ __forceinline__ float warp_sum(float v) {
#pragma unroll
    for (int o = 16; o; o >>= 1) v += __shfl_xor_sync(0xffffffffu, v, o);
    return v;
}

// int64-vs-int32 label layout sniff: odd 32-bit words of an int64 little-endian
// label array are sign extensions in {0,-1}; int32 labels there would be real
// vocab ids. 8 broadcast loads, once per worker block.
__device__ __forceinline__ int sniff_is64(const int* __restrict__ labels32) {
    int ok = 1;
#pragma unroll
    for (int k = 1; k < 16; k += 2) {
        int w = labels32[k];
        if (w != 0 && w != -1) { ok = 0; }
    }
    return ok;
}

// RELEASE-only arrival (thread 0 of each block; 954 total). Release is cheap:
// it orders this block's prior writes (CTA barrier precedes it, and release is
// cumulative) without the L1-invalidate an acquire would cost. Only the ONE
// finishing block pays an acquire fence.
__device__ __forceinline__ unsigned int arrive_release(unsigned int* ctr) {
    unsigned int r;
    asm volatile("atom.release.gpu.global.add.u32 %0, [%1], 1;"
                 : "=r"(r) : "l"(ctr) : "memory");
    return r;
}

// ============================================================================
// K_MAIN: the whole problem in ONE launch.
//   blocks [0,214): chunked InfoNCE, normalize-on-the-fly from raw inputs.
//   blocks [214,954): persistent MLM workers stealing rows in batches of 2.
//   Last arriving block (release/acquire protocol) runs the final combine ->
//   out[0] and resets both counters for the next graph replay.
// MLM: single pass, no max subtraction (logits ~N(0,1): sum(exp)~5e4, fp32-safe).
// InfoNCE: |sim/T| <= ~14.3 -> exp never overflows; accumulate exp directly.
// NO per-thread gpu-scope fences anywhere (R7 lesson: CCTL.IVALL storms).
// ============================================================================
__global__ void __launch_bounds__(256) k_main(
    const float* __restrict__ logits, const int* __restrict__ labels32,
    const float* __restrict__ la, const float* __restrict__ lp,
    const float* __restrict__ ln, const float* __restrict__ qa,
    const float* __restrict__ qp, const float* __restrict__ qn,
    const float* __restrict__ se, float* __restrict__ out)
{
    __shared__ float s_a[8][DIM];        // normalized anchor cache (small path)
    __shared__ float s_part[8][8];       // [warp][anchor] exp-sum partials
    __shared__ float s_red[8];           // block reductions
    __shared__ float s_red2[8];
    __shared__ int   s_r;                // stolen batch base row
    __shared__ int   s_last;

    const int b = blockIdx.x;
    const int t = threadIdx.x;
    const int warp = t >> 5, lane = t & 31;

    if (b >= SMALL_BLOCKS) {
        // ---------------- persistent MLM worker (batch=2 stealing) ----------
        const int is64 = sniff_is64(labels32);      // once per block
        for (;;) {
            if (t == 0) s_r = atomicAdd(&g_next, BATCH);
            __syncthreads();
            const int rbase = s_r;
            if (rbase >= NROWS) break;

#pragma unroll
            for (int k = 0; k < BATCH; k++) {
                const int r = rbase + k;
                if (r >= NROWS) break;
                const int label = is64 ? __ldg(labels32 + 2 * r) : __ldg(labels32 + r);
                if (label < 0) {
                    if (t == 0) g_nv[r] = make_float2(0.f, 0.f);
                    continue;             // dead row: ~no cost beyond label load
                }

                const float* rowp = logits + (size_t)r * VOCAB;
                const int mis  = ((int)((uintptr_t)rowp & 15)) >> 2;   // 0 or 2
                const int head = mis ? (4 - mis) : 0;
                const int n4   = (VOCAB - head) >> 2;
                const int tail = VOCAB - head - n4 * 4;

                const float4* p4 = reinterpret_cast<const float4*>(rowp + head);
                float s0 = 0.f, s1 = 0.f, s2 = 0.f, s3 = 0.f;
#pragma unroll 8
                for (int i = t; i < n4; i += 256) {
                    float4 v = __ldg(p4 + i);
                    s0 += __expf(v.x);
                    s1 += __expf(v.y);
                    s2 += __expf(v.z);
                    s3 += __expf(v.w);
                }
                float s = (s0 + s1) + (s2 + s3);
                if (t == 0) {
                    for (int kk = 0; kk < head; kk++) s += __expf(__ldg(rowp + kk));
                } else if (t == 1) {
                    for (int kk = 0; kk < tail; kk++) s += __expf(__ldg(rowp + head + n4 * 4 + kk));
                }
                s = warp_sum(s);
                if (lane == 0) s_red[warp] = s;
                __syncthreads();
                if (t == 0) {
                    float tot = 0.f;
#pragma unroll
                    for (int w = 0; w < 8; w++) tot += s_red[w];
                    float xl = __ldg(rowp + label);
                    g_nv[r] = make_float2(__logf(tot) - xl, 1.f);
                }
                __syncthreads();          // s_red reuse guard
            }
            __syncthreads();              // s_r reuse guard
        }
    } else {
        // ---------------- small InfoNCE path ----------------
        const float *A, *Pv, *Ng;
        int a0, nbase, nneg, chunk, gidx0, self;
        if (b < 196) {
            int ag = b / 7; chunk = b % 7;
            A = la; Pv = lp; Ng = ln;
            a0 = ag * 8; nbase = chunk * 32; nneg = 32; gidx0 = a0; self = 0;
        } else if (b < 212) {
            int bb = b - 196; int ag = bb / 2; chunk = bb % 2;
            A = qa; Pv = qp; Ng = qn;
            a0 = ag * 8; nbase = chunk * 32; nneg = 32; gidx0 = 224 + a0; self = 0;
        } else {
            int ag = b - 212; chunk = 0;
            A = se; Pv = se; Ng = se;
            a0 = ag * 8; nbase = 0; nneg = 16; gidx0 = 288 + a0; self = 1;
        }

        // warp w: load raw anchor row w, normalize, store to smem
        {
            const float* arow = A + (size_t)(a0 + warp) * DIM;
            float av[DIM / 32];
            float ss = 0.f;
#pragma unroll
            for (int k = 0; k < DIM / 32; k++) {
                float v = __ldg(arow + lane + 32 * k);
                av[k] = v;
                ss += v * v;
            }
            ss = warp_sum(ss);
            float inv = 1.0f / fmaxf(sqrtf(ss), 1e-12f);
#pragma unroll
            for (int k = 0; k < DIM / 32; k++) s_a[warp][lane + 32 * k] = av[k] * inv;
        }
        __syncthreads();

        float p[8];
#pragma unroll
        for (int i = 0; i < 8; i++) p[i] = 0.f;

        for (int jj = warp; jj < nneg; jj += 8) {
            int j = nbase + jj;
            const float* nrow = Ng + (size_t)j * DIM;
            float acc[8];
            float nn = 0.f;
#pragma unroll
            for (int i = 0; i < 8; i++) acc[i] = 0.f;
#pragma unroll 4
            for (int k = 0; k < DIM / 32; k++) {
                int d = lane + 32 * k;
                float nv = __ldg(nrow + d);
                nn += nv * nv;
#pragma unroll
                for (int i = 0; i < 8; i++) acc[i] += nv * s_a[i][d];
            }
            nn = warp_sum(nn);
#pragma unroll
            for (int i = 0; i < 8; i++) acc[i] = warp_sum(acc[i]);
            if (lane == 0) {
                float invn = rsqrtf(fmaxf(nn, 1e-24f));
#pragma unroll
                for (int i = 0; i < 8; i++) {
                    float sim = acc[i] * invn * TEMP_INV;
                    p[i] += __expf(sim);
                    if (self && (a0 + i) == j) g_pos[gidx0 + i] = sim;
                }
            }
        }
        if (lane == 0) {
#pragma unroll
            for (int i = 0; i < 8; i++) s_part[warp][i] = p[i];
        }

        // positives (non-self, chunk 0): warp w -> anchor w
        if (!self && chunk == 0) {
            const float* prow = Pv + (size_t)(a0 + warp) * DIM;
            float d0 = 0.f, pp = 0.f;
#pragma unroll 4
            for (int k = 0; k < DIM / 32; k++) {
                int d = lane + 32 * k;
                float pv = __ldg(prow + d);
                pp += pv * pv;
                d0 += pv * s_a[warp][d];
            }
            d0 = warp_sum(d0);
            pp = warp_sum(pp);
            if (lane == 0)
                g_pos[gidx0 + warp] = d0 * rsqrtf(fmaxf(pp, 1e-24f)) * TEMP_INV;
        }
        __syncthreads();

        if (t < 8) {
            float s = 0.f;
#pragma unroll
            for (int w = 0; w < 8; w++) s += s_part[w][t];
            g_part[(gidx0 + t) * MAXCHUNK + chunk] = s;
        }
    }

    // ---------------- arrival + last-block finish ----------------
    __syncthreads();                      // all block threads' writes precede arrival
    if (t == 0) {
        unsigned int rank = arrive_release(&g_count);
        s_last = (rank == GRID_MAIN - 1);
        if (s_last)                       // the ONLY acquire in the kernel
            asm volatile("fence.acq_rel.gpu;" ::: "memory");
    }
    __syncthreads();
    if (!s_last) return;

    // finishing block (thread 0's acquire + bar.sync -> visibility; L2-hot)
    float contrib = 0.f;
#pragma unroll
    for (int a = t; a < NANCH; a += 256) {
        float pos = g_pos[a];
        if (a < 224) {                    // line
            float s = 0.f;
#pragma unroll
            for (int c = 0; c < 7; c++) s += g_part[a * MAXCHUNK + c];
            contrib += (W_LINE / (float)P_LINE) * (__logf(s + __expf(pos)) - pos);
        } else if (a < 288) {             // quat
            float s = g_part[a * MAXCHUNK + 0] + g_part[a * MAXCHUNK + 1];
            contrib += (W_QUAT / (float)P_QUAT) * (__logf(s + __expf(pos)) - pos);
        } else {                          // sonnet (diag already inside sum)
            float s = g_part[a * MAXCHUNK + 0];
            contrib += (W_SONNET / (float)B_SON) * (__logf(s) - pos);
        }
    }

    float nll = 0.f, cnt = 0.f;
#pragma unroll 4
    for (int i = t; i < NROWS; i += 256) {
        float2 v = g_nv[i];
        nll += v.x;
        cnt += v.y;
    }

    contrib = warp_sum(contrib);
    nll     = warp_sum(nll);
    cnt     = warp_sum(cnt);
    if (lane == 0) { s_red[warp] = contrib; s_red2[warp] = nll; s_part[0][warp] = cnt; }
    __syncthreads();
    if (t == 0) {
        float a = 0.f, bb = 0.f, c = 0.f;
#pragma unroll
        for (int w = 0; w < 8; w++) { a += s_red[w]; bb += s_red2[w]; c += s_part[0][w]; }
        out[0] = a + W_MLM * (bb / fmaxf(c, 1.f));
        g_next  = 0;                      // reset for next graph replay
        g_count = 0;
    }
}

// ============================================================================
extern "C" void kernel_launch(void* const* d_in, const int* in_sizes, int n_in,
                              void* d_out, int out_size)
{
    const float* logits = (const float*)d_in[0];
    const int*   labels = (const int*)  d_in[1];
    const float* la = (const float*)d_in[2];
    const float* lp = (const float*)d_in[3];
    const float* ln = (const float*)d_in[4];
    const float* qa = (const float*)d_in[5];
    const float* qp = (const float*)d_in[6];
    const float* qn = (const float*)d_in[7];
    const float* se = (const float*)d_in[8];

    k_main<<<GRID_MAIN, 256>>>(logits, labels, la, lp, ln, qa, qp, qn, se,
                               (float*)d_out);
}

// round 15
// speedup vs baseline: 1.3750x; 1.3750x over previous
#include <cuda_runtime.h>
#include <math.h>
#include <stdint.h>

#define VOCAB   30522
#define NROWS   4096
#define DIM     768
#define P_LINE  224
#define N_LINE  224
#define P_QUAT  64
#define N_QUAT  64
#define B_SON   16
#define TEMP_INV (1.0f/0.07f)

#define W_MLM    0.5f
#define W_LINE   0.2f
#define W_QUAT   0.2f
#define W_SONNET 0.1f

// global anchor index space: line [0,224), quat [224,288), sonnet [288,304)
#define NANCH    304
#define MAXCHUNK 8
// small-path blocks: 196 line (28 groups x 7 chunks) + 16 quat (8x2) + 2 sonnet
#define SMALL_BLOCKS 214
// persistent MLM workers: 148 SMs x 5 CTAs (reg-limited occupancy)
#define MLM_WORKERS  740
#define GRID_MAIN    (SMALL_BLOCKS + MLM_WORKERS)

// ---- scratch (__device__ globals; no allocations allowed) ----
__device__ float2 g_nv[NROWS];              // {nll, valid} — one write per row
__device__ float  g_pos[NANCH];
__device__ float  g_part[NANCH * MAXCHUNK];
__device__ int    g_next = 0;               // row work-stealing counter; k_final resets

__device__ __forceinline__ float warp_sum(float v) {
#pragma unroll
    for (int o = 16; o; o >>= 1) v += __shfl_xor_sync(0xffffffffu, v, o);
    return v;
}

// int64-vs-int32 label layout sniff: odd 32-bit words of an int64 little-endian
// label array are sign extensions in {0,-1}; int32 labels there would be real
// vocab ids. 8 broadcast loads, once per block.
__device__ __forceinline__ int sniff_is64(const int* __restrict__ labels32) {
    int ok = 1;
#pragma unroll
    for (int k = 1; k < 16; k += 2) {
        int w = labels32[k];
        if (w != 0 && w != -1) { ok = 0; }
    }
    return ok;
}

// ============================================================================
// K_MAIN:
//   blocks [0,214): chunked InfoNCE first, THEN join the MLM steal pool.
//   blocks [214,954): persistent MLM workers from the start.
//   Stealing is software-pipelined: the next atomicAdd is issued before the
//   current row is processed (ping-pong s_rr), hiding the ~600-cycle
//   atomic+label dead chain that capped R9's streaming duty cycle at ~65%.
//   NO gpu-scope fences anywhere (R7 lesson: CCTL.IVALL storms kill the
//   L1tex queue under streaming loads).
// MLM: single pass, no max subtraction (logits ~N(0,1): sum(exp)~5e4, fp32-safe).
// InfoNCE: |sim/T| <= ~14.3 -> exp never overflows; accumulate exp directly.
// ============================================================================
__global__ void __launch_bounds__(256) k_main(
    const float* __restrict__ logits, const int* __restrict__ labels32,
    const float* __restrict__ la, const float* __restrict__ lp,
    const float* __restrict__ ln, const float* __restrict__ qa,
    const float* __restrict__ qp, const float* __restrict__ qn,
    const float* __restrict__ se)
{
    __shared__ float s_a[8][DIM];        // normalized anchor cache (small path)
    __shared__ float s_part[8][8];       // [warp][anchor] exp-sum partials
    __shared__ float s_red[8];           // mlm block reduction
    __shared__ int   s_rr[2];            // ping-pong stolen row indices

    const int b = blockIdx.x;
    const int t = threadIdx.x;
    const int warp = t >> 5, lane = t & 31;

    if (b < SMALL_BLOCKS) {
        // ---------------- small InfoNCE path (then join steal pool) --------
        const float *A, *Pv, *Ng;
        int a0, nbase, nneg, chunk, gidx0, self;
        if (b < 196) {
            int ag = b / 7; chunk = b % 7;
            A = la; Pv = lp; Ng = ln;
            a0 = ag * 8; nbase = chunk * 32; nneg = 32; gidx0 = a0; self = 0;
        } else if (b < 212) {
            int bb = b - 196; int ag = bb / 2; chunk = bb % 2;
            A = qa; Pv = qp; Ng = qn;
            a0 = ag * 8; nbase = chunk * 32; nneg = 32; gidx0 = 224 + a0; self = 0;
        } else {
            int ag = b - 212; chunk = 0;
            A = se; Pv = se; Ng = se;
            a0 = ag * 8; nbase = 0; nneg = 16; gidx0 = 288 + a0; self = 1;
        }

        // warp w: load raw anchor row w, normalize, store to smem
        {
            const float* arow = A + (size_t)(a0 + warp) * DIM;
            float av[DIM / 32];
            float ss = 0.f;
#pragma unroll
            for (int k = 0; k < DIM / 32; k++) {
                float v = __ldg(arow + lane + 32 * k);
                av[k] = v;
                ss += v * v;
            }
            ss = warp_sum(ss);
            float inv = 1.0f / fmaxf(sqrtf(ss), 1e-12f);
#pragma unroll
            for (int k = 0; k < DIM / 32; k++) s_a[warp][lane + 32 * k] = av[k] * inv;
        }
        __syncthreads();

        float p[8];
#pragma unroll
        for (int i = 0; i < 8; i++) p[i] = 0.f;

        for (int jj = warp; jj < nneg; jj += 8) {
            int j = nbase + jj;
            const float* nrow = Ng + (size_t)j * DIM;
            float acc[8];
            float nn = 0.f;
#pragma unroll
            for (int i = 0; i < 8; i++) acc[i] = 0.f;
#pragma unroll 4
            for (int k = 0; k < DIM / 32; k++) {
                int d = lane + 32 * k;
                float nv = __ldg(nrow + d);
                nn += nv * nv;
#pragma unroll
                for (int i = 0; i < 8; i++) acc[i] += nv * s_a[i][d];
            }
            nn = warp_sum(nn);
#pragma unroll
            for (int i = 0; i < 8; i++) acc[i] = warp_sum(acc[i]);
            if (lane == 0) {
                float invn = rsqrtf(fmaxf(nn, 1e-24f));
#pragma unroll
                for (int i = 0; i < 8; i++) {
                    float sim = acc[i] * invn * TEMP_INV;
                    p[i] += __expf(sim);
                    if (self && (a0 + i) == j) g_pos[gidx0 + i] = sim;
                }
            }
        }
        if (lane == 0) {
#pragma unroll
            for (int i = 0; i < 8; i++) s_part[warp][i] = p[i];
        }

        // positives (non-self, chunk 0): warp w -> anchor w
        if (!self && chunk == 0) {
            const float* prow = Pv + (size_t)(a0 + warp) * DIM;
            float d0 = 0.f, pp = 0.f;
#pragma unroll 4
            for (int k = 0; k < DIM / 32; k++) {
                int d = lane + 32 * k;
                float pv = __ldg(prow + d);
                pp += pv * pv;
                d0 += pv * s_a[warp][d];
            }
            d0 = warp_sum(d0);
            pp = warp_sum(pp);
            if (lane == 0)
                g_pos[gidx0 + warp] = d0 * rsqrtf(fmaxf(pp, 1e-24f)) * TEMP_INV;
        }
        __syncthreads();

        if (t < 8) {
            float s = 0.f;
#pragma unroll
            for (int w = 0; w < 8; w++) s += s_part[w][t];
            g_part[(gidx0 + t) * MAXCHUNK + chunk] = s;
        }
        // fall through: join the MLM steal pool
    }

    // ---------------- persistent MLM worker (prefetched stealing) ----------
    const int is64 = sniff_is64(labels32);
    if (t == 0) s_rr[0] = atomicAdd(&g_next, 1);
    __syncthreads();
    int buf = 0;
    for (;;) {
        const int r = s_rr[buf];
        if (r >= NROWS) break;
        if (t == 0) s_rr[buf ^ 1] = atomicAdd(&g_next, 1);   // prefetch next steal

        const int label = is64 ? __ldg(labels32 + 2 * r) : __ldg(labels32 + r);
        if (label >= 0) {
            const float* rowp = logits + (size_t)r * VOCAB;
            const int mis  = ((int)((uintptr_t)rowp & 15)) >> 2;   // floats (0 or 2)
            const int head = mis ? (4 - mis) : 0;
            const int n4   = (VOCAB - head) >> 2;
            const int tail = VOCAB - head - n4 * 4;

            const float4* p4 = reinterpret_cast<const float4*>(rowp + head);
            float s0 = 0.f, s1 = 0.f, s2 = 0.f, s3 = 0.f;
#pragma unroll 8
            for (int i = t; i < n4; i += 256) {
                float4 v = __ldg(p4 + i);
                s0 += __expf(v.x);
                s1 += __expf(v.y);
                s2 += __expf(v.z);
                s3 += __expf(v.w);
            }
            float s = (s0 + s1) + (s2 + s3);
            if (t == 0) {
                for (int k = 0; k < head; k++) s += __expf(__ldg(rowp + k));
            } else if (t == 1) {
                for (int k = 0; k < tail; k++) s += __expf(__ldg(rowp + head + n4 * 4 + k));
            }
            s = warp_sum(s);
            if (lane == 0) s_red[warp] = s;
            __syncthreads();
            if (t == 0) {
                float tot = 0.f;
#pragma unroll
                for (int w = 0; w < 8; w++) tot += s_red[w];
                float xl = __ldg(rowp + label);
                g_nv[r] = make_float2(__logf(tot) - xl, 1.f);
            }
        } else if (t == 0) {
            g_nv[r] = make_float2(0.f, 0.f);
        }
        __syncthreads();          // s_rr[buf^1] published; s_red reusable
        buf ^= 1;
    }
}

// ============================================================================
// K_FINAL: finish per-anchor losses + nll mean -> d_out[0]; reset g_next so
//   the next graph replay starts clean.
// ============================================================================
__global__ void __launch_bounds__(1024) k_final(float* __restrict__ out)
{
    int t = threadIdx.x, lane = t & 31, warp = t >> 5;

    // independent loads issued up front (contiguous 32 KB, L2-hot)
    float2 v0 = g_nv[t];
    float2 v1 = g_nv[t + 1024];
    float2 v2 = g_nv[t + 2048];
    float2 v3 = g_nv[t + 3072];

    float contrib = 0.f;
    if (t < 224) {                       // line
        float s = 0.f;
#pragma unroll
        for (int c = 0; c < 7; c++) s += g_part[t * MAXCHUNK + c];
        float pos = g_pos[t];
        contrib = (W_LINE / (float)P_LINE) * (__logf(s + __expf(pos)) - pos);
    } else if (t < 288) {                // quat
        float s = g_part[t * MAXCHUNK + 0] + g_part[t * MAXCHUNK + 1];
        float pos = g_pos[t];
        contrib = (W_QUAT / (float)P_QUAT) * (__logf(s + __expf(pos)) - pos);
    } else if (t < 304) {                // sonnet (diag already inside sum)
        float s = g_part[t * MAXCHUNK + 0];
        float pos = g_pos[t];
        contrib = (W_SONNET / (float)B_SON) * (__logf(s) - pos);
    }

    float nll = (v0.x + v1.x) + (v2.x + v3.x);
    float cnt = (v0.y + v1.y) + (v2.y + v3.y);

    __shared__ float r0[32], r1[32], r2[32];
    contrib = warp_sum(contrib);
    nll     = warp_sum(nll);
    cnt     = warp_sum(cnt);
    if (lane == 0) { r0[warp] = contrib; r1[warp] = nll; r2[warp] = cnt; }
    __syncthreads();
    if (t < 32) {
        float a = r0[t], bb = r1[t], c = r2[t];
        a = warp_sum(a);
        bb = warp_sum(bb);
        c = warp_sum(c);
        if (t == 0) {
            out[0] = a + W_MLM * (bb / fmaxf(c, 1.f));
            g_next = 0;                  // reset work-stealing counter for next replay
        }
    }
}

// ============================================================================
extern "C" void kernel_launch(void* const* d_in, const int* in_sizes, int n_in,
                              void* d_out, int out_size)
{
    const float* logits = (const float*)d_in[0];
    const int*   labels = (const int*)  d_in[1];
    const float* la = (const float*)d_in[2];
    const float* lp = (const float*)d_in[3];
    const float* ln = (const float*)d_in[4];
    const float* qa = (const float*)d_in[5];
    const float* qp = (const float*)d_in[6];
    const float* qn = (const float*)d_in[7];
    const float* se = (const float*)d_in[8];

    k_main <<<GRID_MAIN, 256>>>(logits, labels, la, lp, ln, qa, qp, qn, se);
    k_final<<<1, 1024>>>((float*)d_out);
}

// round 16
// speedup vs baseline: 1.5013x; 1.0918x over previous
#include <cuda_runtime.h>
#include <math.h>
#include <stdint.h>

#define VOCAB   30522
#define NROWS   4096
#define DIM     768
#define P_LINE  224
#define N_LINE  224
#define P_QUAT  64
#define N_QUAT  64
#define B_SON   16
#define TEMP_INV (1.0f/0.07f)

#define W_MLM    0.5f
#define W_LINE   0.2f
#define W_QUAT   0.2f
#define W_SONNET 0.1f

// global anchor index space: line [0,224), quat [224,288), sonnet [288,304)
#define NANCH    304
#define MAXCHUNK 8
// small-path blocks: 196 line (28 groups x 7 chunks) + 16 quat (8x2) + 2 sonnet
#define SMALL_BLOCKS 214
// persistent MLM workers: 148 SMs x 5 CTAs (reg-limited occupancy)
#define MLM_WORKERS  740
#define GRID_MAIN    (SMALL_BLOCKS + MLM_WORKERS)

// ---- scratch (__device__ globals; no allocations allowed) ----
__device__ float2 g_nv[NROWS];              // {nll, valid} — one write per row
__device__ float  g_pos[NANCH];
__device__ float  g_part[NANCH * MAXCHUNK];
__device__ int    g_next = 0;               // row work-stealing counter; k_final resets

__device__ __forceinline__ float warp_sum(float v) {
#pragma unroll
    for (int o = 16; o; o >>= 1) v += __shfl_xor_sync(0xffffffffu, v, o);
    return v;
}

// int64-vs-int32 label layout sniff: odd 32-bit words of an int64 little-endian
// label array are sign extensions in {0,-1}; int32 labels there would be real
// vocab ids. 8 broadcast loads, once per worker block.
__device__ __forceinline__ int sniff_is64(const int* __restrict__ labels32) {
    int ok = 1;
#pragma unroll
    for (int k = 1; k < 16; k += 2) {
        int w = labels32[k];
        if (w != 0 && w != -1) { ok = 0; }
    }
    return ok;
}

// ============================================================================
// K_MAIN (identical to the best-measured R9 kernel):
//   blocks [0,214): chunked InfoNCE, normalize-on-the-fly from raw inputs.
//   blocks [214,954): persistent MLM workers pulling rows via atomicAdd.
//   NO gpu-scope fences anywhere (R7 lesson: CCTL.IVALL storms kill the
//   L1tex queue under streaming loads).
// MLM: single pass, no max subtraction (logits ~N(0,1): sum(exp)~5e4, fp32-safe).
// InfoNCE: |sim/T| <= ~14.3 -> exp never overflows; accumulate exp directly.
// ============================================================================
__global__ void __launch_bounds__(256) k_main(
    const float* __restrict__ logits, const int* __restrict__ labels32,
    const float* __restrict__ la, const float* __restrict__ lp,
    const float* __restrict__ ln, const float* __restrict__ qa,
    const float* __restrict__ qp, const float* __restrict__ qn,
    const float* __restrict__ se)
{
    __shared__ float s_a[8][DIM];        // normalized anchor cache (small path)
    __shared__ float s_part[8][8];       // [warp][anchor] exp-sum partials
    __shared__ float s_red[8];           // mlm block reduction
    __shared__ int   s_r;                // stolen row index

    const int b = blockIdx.x;
    const int t = threadIdx.x;
    const int warp = t >> 5, lane = t & 31;

    if (b >= SMALL_BLOCKS) {
        // ---------------- persistent MLM worker ----------------
        const int is64 = sniff_is64(labels32);      // once per block
        for (;;) {
            if (t == 0) s_r = atomicAdd(&g_next, 1);
            __syncthreads();
            const int r = s_r;
            if (r >= NROWS) break;

            const int label = is64 ? __ldg(labels32 + 2 * r) : __ldg(labels32 + r);
            if (label < 0) {
                if (t == 0) g_nv[r] = make_float2(0.f, 0.f);
                __syncthreads();          // s_r reuse guard
                continue;
            }

            const float* rowp = logits + (size_t)r * VOCAB;
            const int mis  = ((int)((uintptr_t)rowp & 15)) >> 2;   // floats (0 or 2)
            const int head = mis ? (4 - mis) : 0;
            const int n4   = (VOCAB - head) >> 2;
            const int tail = VOCAB - head - n4 * 4;

            const float4* p4 = reinterpret_cast<const float4*>(rowp + head);
            float s0 = 0.f, s1 = 0.f, s2 = 0.f, s3 = 0.f;
#pragma unroll 8
            for (int i = t; i < n4; i += 256) {
                float4 v = __ldg(p4 + i);
                s0 += __expf(v.x);
                s1 += __expf(v.y);
                s2 += __expf(v.z);
                s3 += __expf(v.w);
            }
            float s = (s0 + s1) + (s2 + s3);
            if (t == 0) {
                for (int k = 0; k < head; k++) s += __expf(__ldg(rowp + k));
            } else if (t == 1) {
                for (int k = 0; k < tail; k++) s += __expf(__ldg(rowp + head + n4 * 4 + k));
            }
            s = warp_sum(s);
            if (lane == 0) s_red[warp] = s;
            __syncthreads();
            if (t == 0) {
                float tot = 0.f;
#pragma unroll
                for (int w = 0; w < 8; w++) tot += s_red[w];
                float xl = __ldg(rowp + label);
                g_nv[r] = make_float2(__logf(tot) - xl, 1.f);
            }
            __syncthreads();              // s_red / s_r reuse guard
        }
        return;
    }

    // ---------------- small InfoNCE path ----------------
    const float *A, *Pv, *Ng;
    int a0, nbase, nneg, chunk, gidx0, self;
    if (b < 196) {
        int ag = b / 7; chunk = b % 7;
        A = la; Pv = lp; Ng = ln;
        a0 = ag * 8; nbase = chunk * 32; nneg = 32; gidx0 = a0; self = 0;
    } else if (b < 212) {
        int bb = b - 196; int ag = bb / 2; chunk = bb % 2;
        A = qa; Pv = qp; Ng = qn;
        a0 = ag * 8; nbase = chunk * 32; nneg = 32; gidx0 = 224 + a0; self = 0;
    } else {
        int ag = b - 212; chunk = 0;
        A = se; Pv = se; Ng = se;
        a0 = ag * 8; nbase = 0; nneg = 16; gidx0 = 288 + a0; self = 1;
    }

    // warp w: load raw anchor row w, normalize, store to smem
    {
        const float* arow = A + (size_t)(a0 + warp) * DIM;
        float av[DIM / 32];
        float ss = 0.f;
#pragma unroll
        for (int k = 0; k < DIM / 32; k++) {
            float v = __ldg(arow + lane + 32 * k);
            av[k] = v;
            ss += v * v;
        }
        ss = warp_sum(ss);
        float inv = 1.0f / fmaxf(sqrtf(ss), 1e-12f);
#pragma unroll
        for (int k = 0; k < DIM / 32; k++) s_a[warp][lane + 32 * k] = av[k] * inv;
    }
    __syncthreads();

    float p[8];
#pragma unroll
    for (int i = 0; i < 8; i++) p[i] = 0.f;

    for (int jj = warp; jj < nneg; jj += 8) {
        int j = nbase + jj;
        const float* nrow = Ng + (size_t)j * DIM;
        float acc[8];
        float nn = 0.f;
#pragma unroll
        for (int i = 0; i < 8; i++) acc[i] = 0.f;
#pragma unroll 4
        for (int k = 0; k < DIM / 32; k++) {
            int d = lane + 32 * k;
            float nv = __ldg(nrow + d);
            nn += nv * nv;
#pragma unroll
            for (int i = 0; i < 8; i++) acc[i] += nv * s_a[i][d];
        }
        nn = warp_sum(nn);
#pragma unroll
        for (int i = 0; i < 8; i++) acc[i] = warp_sum(acc[i]);
        if (lane == 0) {
            float invn = rsqrtf(fmaxf(nn, 1e-24f));
#pragma unroll
            for (int i = 0; i < 8; i++) {
                float sim = acc[i] * invn * TEMP_INV;
                p[i] += __expf(sim);
                if (self && (a0 + i) == j) g_pos[gidx0 + i] = sim;
            }
        }
    }
    if (lane == 0) {
#pragma unroll
        for (int i = 0; i < 8; i++) s_part[warp][i] = p[i];
    }

    // positives (non-self, chunk 0): warp w -> anchor w, normalize on the fly
    if (!self && chunk == 0) {
        const float* prow = Pv + (size_t)(a0 + warp) * DIM;
        float d0 = 0.f, pp = 0.f;
#pragma unroll 4
        for (int k = 0; k < DIM / 32; k++) {
            int d = lane + 32 * k;
            float pv = __ldg(prow + d);
            pp += pv * pv;
            d0 += pv * s_a[warp][d];
        }
        d0 = warp_sum(d0);
        pp = warp_sum(pp);
        if (lane == 0)
            g_pos[gidx0 + warp] = d0 * rsqrtf(fmaxf(pp, 1e-24f)) * TEMP_INV;
    }
    __syncthreads();

    if (t < 8) {
        float s = 0.f;
#pragma unroll
        for (int w = 0; w < 8; w++) s += s_part[w][t];
        g_part[(gidx0 + t) * MAXCHUNK + chunk] = s;
    }
}

// ============================================================================
// K_FINAL: PDL secondary. Launched with programmaticStreamSerialization so its
//   block is resident during k_main; cudaGridDependencySynchronize() parks it
//   until k_main fully completes (no early trigger in k_main -> completion
//   semantics, full memory visibility), eliminating launch gap + startup.
// ============================================================================
__global__ void __launch_bounds__(1024) k_final(float* __restrict__ out)
{
    cudaGridDependencySynchronize();     // wait for k_main completion

    int t = threadIdx.x, lane = t & 31, warp = t >> 5;

    // independent loads issued up front (contiguous 32 KB, L2-hot)
    float2 v0 = g_nv[t];
    float2 v1 = g_nv[t + 1024];
    float2 v2 = g_nv[t + 2048];
    float2 v3 = g_nv[t + 3072];

    float contrib = 0.f;
    if (t < 224) {                       // line
        float s = 0.f;
#pragma unroll
        for (int c = 0; c < 7; c++) s += g_part[t * MAXCHUNK + c];
        float pos = g_pos[t];
        contrib = (W_LINE / (float)P_LINE) * (__logf(s + __expf(pos)) - pos);
    } else if (t < 288) {                // quat
        float s = g_part[t * MAXCHUNK + 0] + g_part[t * MAXCHUNK + 1];
        float pos = g_pos[t];
        contrib = (W_QUAT / (float)P_QUAT) * (__logf(s + __expf(pos)) - pos);
    } else if (t < 304) {                // sonnet (diag already inside sum)
        float s = g_part[t * MAXCHUNK + 0];
        float pos = g_pos[t];
        contrib = (W_SONNET / (float)B_SON) * (__logf(s) - pos);
    }

    float nll = (v0.x + v1.x) + (v2.x + v3.x);
    float cnt = (v0.y + v1.y) + (v2.y + v3.y);

    __shared__ float r0[32], r1[32], r2[32];
    contrib = warp_sum(contrib);
    nll     = warp_sum(nll);
    cnt     = warp_sum(cnt);
    if (lane == 0) { r0[warp] = contrib; r1[warp] = nll; r2[warp] = cnt; }
    __syncthreads();
    if (t < 32) {
        float a = r0[t], bb = r1[t], c = r2[t];
        a = warp_sum(a);
        bb = warp_sum(bb);
        c = warp_sum(c);
        if (t == 0) {
            out[0] = a + W_MLM * (bb / fmaxf(c, 1.f));
            g_next = 0;                  // reset work-stealing counter for next replay
        }
    }
}

// ============================================================================
extern "C" void kernel_launch(void* const* d_in, const int* in_sizes, int n_in,
                              void* d_out, int out_size)
{
    const float* logits = (const float*)d_in[0];
    const int*   labels = (const int*)  d_in[1];
    const float* la = (const float*)d_in[2];
    const float* lp = (const float*)d_in[3];
    const float* ln = (const float*)d_in[4];
    const float* qa = (const float*)d_in[5];
    const float* qp = (const float*)d_in[6];
    const float* qn = (const float*)d_in[7];
    const float* se = (const float*)d_in[8];

    k_main<<<GRID_MAIN, 256>>>(logits, labels, la, lp, ln, qa, qp, qn, se);

    // k_final via PDL: launch overlaps k_main; grid-dependency sync inside.
    cudaLaunchConfig_t cfg = {};
    cfg.gridDim  = dim3(1, 1, 1);
    cfg.blockDim = dim3(1024, 1, 1);
    cfg.dynamicSmemBytes = 0;
    cfg.stream = 0;                      // same (legacy) stream as k_main
    cudaLaunchAttribute attrs[1];
    attrs[0].id = cudaLaunchAttributeProgrammaticStreamSerialization;
    attrs[0].val.programmaticStreamSerializationAllowed = 1;
    cfg.attrs = attrs;
    cfg.numAttrs = 1;
    cudaLaunchKernelEx(&cfg, k_final, (float*)d_out);
}